// round 16
// baseline (speedup 1.0000x reference)
#include <cuda_runtime.h>
#include <cuda_fp16.h>
#include <math.h>
#include <cstdint>

#define T_LEN 512
#define BSZ   256
#define DIM   512
#define HID   512
#define N4    (4 * HID)       /* 2048 */

// Scratch: input projections [T][B][4H].
__device__ float g_Y[268435456];          // 131072 * 2048
// fp16 copies of X and W (W rows: gate*512 + r, gates f,i,o,a).
__device__ __half g_Xf[67108864];         // 131072 * 512
__device__ __half g_Wf[1048576];          // 2048 * 512
// h(t) in mma A-fragment layout: [16 groups][2 phases][16384 bytes].
__device__ __align__(16) unsigned char g_hfrag[524288];
// Per-mTile-group barrier: group g uses [g*64] = count, [g*64+32] = gen.
__device__ unsigned g_sync2[1024];
// GEMM progress: bitmask per timestep (32 tiles each). Reset after each run.
__device__ unsigned g_prog[512];
// Recurrence completion counter (monotonic across replays).
__device__ unsigned g_done2;

// ============================================================================
// helpers
// ============================================================================
__device__ __forceinline__ uint32_t smem_u32(const void* p) {
    uint32_t a;
    asm("{ .reg .u64 t; cvta.to.shared.u64 t, %1; cvt.u32.u64 %0, t; }"
        : "=r"(a) : "l"(p));
    return a;
}
__device__ __forceinline__ void ldsm_x4(uint32_t& r0, uint32_t& r1,
                                        uint32_t& r2, uint32_t& r3,
                                        uint32_t addr) {
    asm volatile("ldmatrix.sync.aligned.m8n8.x4.shared.b16 {%0,%1,%2,%3}, [%4];"
                 : "=r"(r0), "=r"(r1), "=r"(r2), "=r"(r3) : "r"(addr));
}
__device__ __forceinline__ void mma16816(float* c, const uint32_t* a,
                                         uint32_t b0, uint32_t b1) {
    asm volatile(
        "mma.sync.aligned.m16n8k16.row.col.f32.f16.f16.f32 "
        "{%0,%1,%2,%3}, {%4,%5,%6,%7}, {%8,%9}, {%0,%1,%2,%3};"
        : "+f"(c[0]), "+f"(c[1]), "+f"(c[2]), "+f"(c[3])
        : "r"(a[0]), "r"(a[1]), "r"(a[2]), "r"(a[3]), "r"(b0), "r"(b1));
}
#define CP_ASYNC16(dst, src) \
    asm volatile("cp.async.cg.shared.global [%0], [%1], 16;" \
                 :: "r"(dst), "l"(src) : "memory")
#define CP_COMMIT() asm volatile("cp.async.commit_group;" ::: "memory")
#define CP_WAIT(n)  asm volatile("cp.async.wait_group %0;" :: "n"(n) : "memory")

__device__ __forceinline__ unsigned atom_add_acqrel(unsigned* p, unsigned v) {
    unsigned old;
    asm volatile("atom.acq_rel.gpu.global.add.u32 %0, [%1], %2;"
                 : "=r"(old) : "l"(p), "r"(v) : "memory");
    return old;
}
__device__ __forceinline__ unsigned ld_acquire(const unsigned* p) {
    unsigned v;
    asm volatile("ld.acquire.gpu.global.u32 %0, [%1];"
                 : "=r"(v) : "l"(p) : "memory");
    return v;
}
__device__ __forceinline__ void st_release(unsigned* p, unsigned v) {
    asm volatile("st.release.gpu.global.u32 [%0], %1;"
                 :: "l"(p), "r"(v) : "memory");
}
__device__ __forceinline__ void red_add_release(unsigned* p, unsigned v) {
    asm volatile("red.release.gpu.global.add.u32 [%0], %1;"
                 :: "l"(p), "r"(v) : "memory");
}
__device__ __forceinline__ void red_or_release(unsigned* p, unsigned v) {
    asm volatile("red.release.gpu.global.or.b32 [%0], %1;"
                 :: "l"(p), "r"(v) : "memory");
}
__device__ __forceinline__ uint4 ldg_cg_v4(const void* p) {
    uint4 v;
    asm volatile("ld.global.cg.v4.u32 {%0,%1,%2,%3}, [%4];"
                 : "=r"(v.x), "=r"(v.y), "=r"(v.z), "=r"(v.w) : "l"(p));
    return v;
}

// ============================================================================
// One-time fp32 -> fp16 conversion kernels.
// ============================================================================
__global__ __launch_bounds__(256) void convert_x_h(const float* __restrict__ X) {
    size_t i = (size_t)blockIdx.x * blockDim.x + threadIdx.x;   // per float4
    float4 v = reinterpret_cast<const float4*>(X)[i];
    __half2 a = __floats2half2_rn(v.x, v.y);
    __half2 b = __floats2half2_rn(v.z, v.w);
    reinterpret_cast<uint2*>(g_Xf)[i] =
        make_uint2(*reinterpret_cast<uint32_t*>(&a),
                   *reinterpret_cast<uint32_t*>(&b));
}
__global__ __launch_bounds__(256) void convert_w_h(
    const float* __restrict__ Wf, const float* __restrict__ Wi,
    const float* __restrict__ Wo, const float* __restrict__ Wa) {
    size_t i = (size_t)blockIdx.x * blockDim.x + threadIdx.x;   // per float4
    int gate = (int)(i >> 16);
    const float* W = (gate == 0) ? Wf : (gate == 1) ? Wi : (gate == 2) ? Wo : Wa;
    float4 v = reinterpret_cast<const float4*>(W)[i & 65535];
    __half2 a = __floats2half2_rn(v.x, v.y);
    __half2 b = __floats2half2_rn(v.z, v.w);
    reinterpret_cast<uint2*>(g_Wf)[i] =
        make_uint2(*reinterpret_cast<uint32_t*>(&a),
                   *reinterpret_cast<uint32_t*>(&b));
}

// ============================================================================
// GEMM1 via fp16 mma.sync, cp.async 2-stage pipeline (round-8 core) + per-t
// progress bit posted on completion.
// ============================================================================
__global__ __launch_bounds__(256, 2) void gemm_xproj_mma(
    const float* __restrict__ bf, const float* __restrict__ bi,
    const float* __restrict__ bo)
{
    extern __shared__ __align__(128) char smem[];
    const uint32_t sb = smem_u32(smem);

    const int tid  = threadIdx.x;
    const int lane = tid & 31;
    const int wid  = tid >> 5;
    const int wm   = wid >> 1;
    const int wn   = wid & 1;

    const int nTile = blockIdx.x;
    const int mBase = blockIdx.y * 128;
    const int gate  = nTile >> 2;
    const int rowG  = (nTile & 3) * 128;
    const float* bias = (gate == 0) ? bf : (gate == 1) ? bi : (gate == 2) ? bo : nullptr;

    const __half* A = g_Xf + (size_t)mBase * DIM;
    const __half* B = g_Wf + (size_t)nTile * 128 * DIM;

    float c[2][8][4];
#pragma unroll
    for (int mf = 0; mf < 2; mf++)
#pragma unroll
        for (int nf = 0; nf < 8; nf++)
#pragma unroll
            for (int q = 0; q < 4; q++) c[mf][nf][q] = 0.f;

    auto stage = [&](int chunk, int s) {
        const int kb = chunk * 64;
        const uint32_t sOff = (uint32_t)s * 32768;
#pragma unroll
        for (int it = 0; it < 4; it++) {
            int idx = tid + it * 256;
            int row = idx >> 3;
            int ch  = idx & 7;
            uint32_t off = sOff + (uint32_t)row * 128 + ((ch ^ (row & 7)) << 4);
            const size_t g = (size_t)row * DIM + kb + ch * 8;
            CP_ASYNC16(sb + off,         A + g);
            CP_ASYNC16(sb + off + 16384, B + g);
        }
        CP_COMMIT();
    };

    stage(0, 0);

    for (int chunk = 0; chunk < 8; chunk++) {
        if (chunk < 7) {
            stage(chunk + 1, (chunk + 1) & 1);
            CP_WAIT(1);
        } else {
            CP_WAIT(0);
        }
        __syncthreads();

        const uint32_t sOff = (uint32_t)(chunk & 1) * 32768;
        const uint32_t AS = sOff, BS = sOff + 16384;

#pragma unroll
        for (int ks = 0; ks < 4; ks++) {
            const int chv = ks * 2 + (lane >> 4);

            uint32_t a[2][4];
#pragma unroll
            for (int mf = 0; mf < 2; mf++) {
                const int row = wm * 32 + mf * 16 + (lane & 15);
                const uint32_t addr =
                    sb + AS + (uint32_t)row * 128 + (((chv ^ (row & 7))) << 4);
                ldsm_x4(a[mf][0], a[mf][1], a[mf][2], a[mf][3], addr);
            }
            uint32_t b[4][4];
#pragma unroll
            for (int np = 0; np < 4; np++) {
                const int row = wn * 64 + np * 16 + (lane & 15);
                const uint32_t addr =
                    sb + BS + (uint32_t)row * 128 + (((chv ^ (row & 7))) << 4);
                ldsm_x4(b[np][0], b[np][1], b[np][2], b[np][3], addr);
            }
#pragma unroll
            for (int mf = 0; mf < 2; mf++)
#pragma unroll
                for (int nf = 0; nf < 8; nf++) {
                    const int np = nf >> 1, s = nf & 1;
                    mma16816(c[mf][nf], a[mf], b[np][s], b[np][s + 2]);
                }
        }
        __syncthreads();
    }

    const int colBase = nTile * 128 + wn * 64 + (lane & 3) * 2;
    const int rBase   = mBase + wm * 32 + (lane >> 2);
#pragma unroll
    for (int nf = 0; nf < 8; nf++) {
        const int col = colBase + nf * 8;
        const int ln  = wn * 64 + nf * 8 + (lane & 3) * 2;
        float b0 = bias ? __ldg(bias + rowG + ln)     : 0.f;
        float b1 = bias ? __ldg(bias + rowG + ln + 1) : 0.f;
#pragma unroll
        for (int mf = 0; mf < 2; mf++) {
            const size_t r0 = (size_t)(rBase + mf * 16);
            float2 o0 = make_float2(c[mf][nf][0] + b0, c[mf][nf][1] + b1);
            float2 o1 = make_float2(c[mf][nf][2] + b0, c[mf][nf][3] + b1);
            *reinterpret_cast<float2*>(g_Y + r0 * N4 + col)       = o0;
            *reinterpret_cast<float2*>(g_Y + (r0 + 8) * N4 + col) = o1;
        }
    }

    // Post completion bit for this tile's timestep.
    __syncthreads();
    if (tid == 0) {
        const int tstep = blockIdx.y >> 1;               // 256 rows per t
        const unsigned bit = 1u << (blockIdx.x + 16 * (blockIdx.y & 1));
        red_or_release(&g_prog[tstep], bit);
    }
}

// ============================================================================
// Persistent tensor-core recurrence (R15 protocol, W via smem ldsm to keep
// regs <= 128 so GEMM CTAs can co-reside). Polls g_prog[t] before consuming
// Y(t) -- GEMM runs concurrently on a forked stream.
// ============================================================================
__device__ __forceinline__ float sigf(float x) {
    return 1.f / (1.f + __expf(-x));
}
__device__ __forceinline__ float tanh_fast(float x) {
    return 2.f / (1.f + __expf(-2.f * x)) - 1.f;
}

__global__ __launch_bounds__(256, 2) void lstm_persistent_tc(
    const float* __restrict__ Waa,
    const float* __restrict__ ba,
    float*       __restrict__ out,
    float*       __restrict__ hn)
{
    extern __shared__ __align__(128) char sm[];
    const uint32_t sb = smem_u32(sm);

    const int tid  = threadIdx.x;
    const int lane = tid & 31;
    const int wid  = tid >> 5;                 // 0..7: n-subtile
    const int grp  = blockIdx.x >> 3;          // mTile group 0..15
    const int rank = blockIdx.x & 7;           // nTile rank
    const int m0   = grp * 16;
    const int n0   = rank * 64;

    // done-counter base (read early; only bid 0 uses it).
    unsigned done0 = 0;
    if (blockIdx.x == 0 && tid == 0) done0 = ld_acquire(&g_done2);

    // --- one-time: Waa[n0+n][k] -> smem fp16 (swizzled) ---
#pragma unroll
    for (int i = 0; i < 16; i++) {
        int idx = tid + i * 256;          // n(0..63) x chunk(0..63)
        int n = idx >> 6;
        int c = idx & 63;
        const float* src = Waa + (size_t)(n0 + n) * HID + c * 8;
        float4 v0 = *reinterpret_cast<const float4*>(src);
        float4 v1 = *reinterpret_cast<const float4*>(src + 4);
        __half2 hh[4];
        hh[0] = __floats2half2_rn(v0.x, v0.y);
        hh[1] = __floats2half2_rn(v0.z, v0.w);
        hh[2] = __floats2half2_rn(v1.x, v1.y);
        hh[3] = __floats2half2_rn(v1.z, v1.w);
        uint32_t off = (uint32_t)n * 1024 + ((c ^ (n & 7)) << 4);
        *reinterpret_cast<uint4*>(sm + off) = *reinterpret_cast<uint4*>(hh);
    }

    // Per-thread coordinates (mma c-frag layout).
    const int nn   = n0 + wid * 8 + (lane & 3) * 2;
    const int row0 = lane >> 2;
    const int mr0  = m0 + row0;
    const int mr1  = mr0 + 8;
    const float bav0 = ba[nn];
    const float bav1 = ba[nn + 1];

    // Producer fragment address.
    const uint32_t sP = (uint32_t)(nn >> 4);
    const uint32_t lP = (uint32_t)row0 * 4 + (uint32_t)((nn >> 1) & 3);
    const uint32_t wP = (uint32_t)((nn >> 3) & 1) * 2;
    const uint32_t prodOff = sP * 512 + lP * 16 + wP * 4;

    unsigned char* fragBase = g_hfrag + (size_t)grp * 32768;
    unsigned* cntp = &g_sync2[grp * 64];
    unsigned* genp = &g_sync2[grp * 64 + 32];

    // B (W_aa) ldsm statics.
    const int rB = wid * 8 + (lane & 7);
    const uint32_t bRow = sb + (uint32_t)rB * 1024;
    const int swB = rB & 7;

    unsigned gen0 = 0;
    if (tid == 0) {
        gen0 = ld_acquire(genp);
        // Wait for GEMM to finish timestep 0 before first Y read.
        while (ld_acquire(&g_prog[0]) != 0xFFFFFFFFu) { }
    }
    __syncthreads();

    float cc[4];
#pragma unroll
    for (int j = 0; j < 4; j++) cc[j] = 0.f;

    // Y prefetch for t=0.
    float2 pf[2][4];
    {
        const float* yb = g_Y;
#pragma unroll
        for (int g = 0; g < 4; g++) {
            pf[0][g] = *reinterpret_cast<const float2*>(
                yb + (size_t)mr0 * N4 + g * HID + nn);
            pf[1][g] = *reinterpret_cast<const float2*>(
                yb + (size_t)mr1 * N4 + g * HID + nn);
        }
    }

    for (int t = 0; t < T_LEN; t++) {
        float c0[4] = {0.f, 0.f, 0.f, 0.f};
        float c1[4] = {0.f, 0.f, 0.f, 0.f};
        float c2[4] = {0.f, 0.f, 0.f, 0.f};
        float c3[4] = {0.f, 0.f, 0.f, 0.f};

        if (t > 0) {
            if (tid == 0) {
                const unsigned target = gen0 + (unsigned)t;
                while ((int)(ld_acquire(genp) - target) < 0) { }
            }
            __syncthreads();

            const unsigned char* fb =
                fragBase + (size_t)((t - 1) & 1) * 16384 + (uint32_t)lane * 16;
#pragma unroll
            for (int j = 0; j < 16; j++) {    // k32 steps
                uint4 av0 = ldg_cg_v4(fb + (uint32_t)(2 * j) * 512);
                uint4 av1 = ldg_cg_v4(fb + (uint32_t)(2 * j + 1) * 512);
                uint32_t a0[4] = {av0.x, av0.y, av0.z, av0.w};
                uint32_t a1[4] = {av1.x, av1.y, av1.z, av1.w};
                const int chB = j * 4 + (lane >> 3);
                uint32_t b[4];
                ldsm_x4(b[0], b[1], b[2], b[3], bRow + ((chB ^ swB) << 4));
                if (j & 1) {
                    mma16816(c2, a0, b[0], b[1]);
                    mma16816(c3, a1, b[2], b[3]);
                } else {
                    mma16816(c0, a0, b[0], b[1]);
                    mma16816(c1, a1, b[2], b[3]);
                }
            }
        }

        float acc[4];
#pragma unroll
        for (int j = 0; j < 4; j++)
            acc[j] = (c0[j] + c2[j]) + (c1[j] + c3[j]);

        float hv[4];
#pragma unroll
        for (int r = 0; r < 2; r++) {
            float a0 = acc[r * 2 + 0] + bav0;
            float a1 = acc[r * 2 + 1] + bav1;
            float f0 = sigf(pf[r][0].x + a0), f1 = sigf(pf[r][0].y + a1);
            float i0 = sigf(pf[r][1].x + a0), i1 = sigf(pf[r][1].y + a1);
            float o0 = sigf(pf[r][2].x + a0), o1 = sigf(pf[r][2].y + a1);
            float g0 = tanh_fast(pf[r][3].x + a0);
            float g1 = tanh_fast(pf[r][3].y + a1);
            cc[r * 2 + 0] = f0 * cc[r * 2 + 0] + i0 * g0;
            cc[r * 2 + 1] = f1 * cc[r * 2 + 1] + i1 * g1;
            hv[r * 2 + 0] = o0 * tanh_fast(cc[r * 2 + 0]);
            hv[r * 2 + 1] = o1 * tanh_fast(cc[r * 2 + 1]);
        }

        if (t < T_LEN - 1) {
            __half2 h2a = __floats2half2_rn(hv[0], hv[1]);
            __half2 h2b = __floats2half2_rn(hv[2], hv[3]);
            uint2 v = make_uint2(*reinterpret_cast<uint32_t*>(&h2a),
                                 *reinterpret_cast<uint32_t*>(&h2b));
            *reinterpret_cast<uint2*>(
                fragBase + (size_t)(t & 1) * 16384 + prodOff) = v;
        }

        {
            float* ob = out + ((size_t)t * BSZ) * HID;
            *reinterpret_cast<float2*>(ob + (size_t)mr0 * HID + nn) =
                make_float2(hv[0], hv[1]);
            *reinterpret_cast<float2*>(ob + (size_t)mr1 * HID + nn) =
                make_float2(hv[2], hv[3]);
            if (hn && t == T_LEN - 1) {
                *reinterpret_cast<float2*>(hn + (size_t)mr0 * HID + nn) =
                    make_float2(hv[0], hv[1]);
                *reinterpret_cast<float2*>(hn + (size_t)mr1 * HID + nn) =
                    make_float2(hv[2], hv[3]);
            }
        }

        if (t < T_LEN - 1) {
            // Ensure GEMM finished Y(t+1), then prefetch it.
            if (tid == 0) {
                while (ld_acquire(&g_prog[t + 1]) != 0xFFFFFFFFu) { }
            }
            __syncthreads();        // also orders frag stores before arrive

            const float* yb = g_Y + (size_t)(t + 1) * BSZ * N4;
#pragma unroll
            for (int g = 0; g < 4; g++) {
                pf[0][g] = *reinterpret_cast<const float2*>(
                    yb + (size_t)mr0 * N4 + g * HID + nn);
                pf[1][g] = *reinterpret_cast<const float2*>(
                    yb + (size_t)mr1 * N4 + g * HID + nn);
            }

            if (tid == 0) {
                unsigned old = atom_add_acqrel(cntp, 1u);
                if (old == 7u) {
                    *cntp = 0u;
                    st_release(genp, gen0 + (unsigned)(t + 1));
                }
            }
        }
    }

    // Completion + replay-safe g_prog reset (bid 0 waits for all 128).
    __syncthreads();
    if (tid == 0) red_add_release(&g_done2, 1u);
    if (blockIdx.x == 0 && tid == 0) {
        const unsigned target = done0 + 128u;
        while ((int)(ld_acquire(&g_done2) - target) < 0) { }
        for (int i = 0; i < 512; i++) g_prog[i] = 0u;
        __threadfence();
    }
}

// ---------------------------------------------------------------------------
extern "C" void kernel_launch(void* const* d_in, const int* in_sizes, int n_in,
                              void* d_out, int out_size)
{
    (void)in_sizes; (void)n_in;
    const float* X   = (const float*)d_in[0];
    const float* Wf  = (const float*)d_in[1];
    const float* Wi  = (const float*)d_in[2];
    const float* Wo  = (const float*)d_in[3];
    const float* Wa  = (const float*)d_in[4];
    const float* Waa = (const float*)d_in[5];
    const float* bf  = (const float*)d_in[6];
    const float* bi  = (const float*)d_in[7];
    const float* bo  = (const float*)d_in[8];
    const float* ba  = (const float*)d_in[9];
    float* out = (float*)d_out;

    const int gemm_smem = 65536;    // 64 KB
    const int rec_smem  = 65536;    // 64 KB (W resident)

    static cudaStream_t s2 = nullptr;
    static cudaEvent_t evA = nullptr, evB = nullptr;
    static bool attr_set = false;
    if (!attr_set) {
        cudaFuncSetAttribute(gemm_xproj_mma,
                             cudaFuncAttributeMaxDynamicSharedMemorySize,
                             gemm_smem);
        cudaFuncSetAttribute(lstm_persistent_tc,
                             cudaFuncAttributeMaxDynamicSharedMemorySize,
                             rec_smem);
        int loPri = 0, hiPri = 0;
        cudaDeviceGetStreamPriorityRange(&loPri, &hiPri);
        cudaStreamCreateWithPriority(&s2, cudaStreamNonBlocking, loPri);
        cudaEventCreateWithFlags(&evA, cudaEventDisableTiming);
        cudaEventCreateWithFlags(&evB, cudaEventDisableTiming);
        attr_set = true;
    }

    // Conversions on the main stream.
    convert_x_h<<<65536, 256>>>(X);
    convert_w_h<<<1024, 256>>>(Wf, Wi, Wo, Wa);

    // Fork: GEMM on low-priority stream s2, recurrence on main stream.
    cudaEventRecord(evA, 0);
    cudaStreamWaitEvent(s2, evA, 0);

    dim3 g1(16, 1024);
    gemm_xproj_mma<<<g1, 256, gemm_smem, s2>>>(bf, bi, bo);
    cudaEventRecord(evB, s2);

    const size_t step_elems = (size_t)BSZ * HID;
    const size_t outs_elems = (size_t)T_LEN * step_elems;
    float* hn_ptr = ((size_t)out_size >= outs_elems + step_elems)
                        ? out + outs_elems : nullptr;

    lstm_persistent_tc<<<128, 256, rec_smem>>>(Waa, ba, out, hn_ptr);

    // Join: main stream waits for the GEMM branch.
    cudaStreamWaitEvent(0, evB, 0);
}

// round 17
// speedup vs baseline: 1.2181x; 1.2181x over previous
#include <cuda_runtime.h>
#include <cuda_fp16.h>
#include <math.h>
#include <cstdint>

#define T_LEN 512
#define BSZ   256
#define DIM   512
#define HID   512
#define N4    (4 * HID)       /* 2048 */

// Scratch: input projections [T][B][4H].
__device__ float g_Y[268435456];          // 131072 * 2048
// fp16 copies of X and W (W rows: gate*512 + r, gates f,i,o,a).
__device__ __half g_Xf[67108864];         // 131072 * 512
__device__ __half g_Wf[1048576];          // 2048 * 512
// h(t) in mma A-fragment layout: [16 groups][2 phases][16384 bytes].
__device__ __align__(16) unsigned char g_hfrag[524288];
// Per-(group,rank) progress flags, 128B apart: g_cnt[(grp*8+rank)*32].
__device__ unsigned g_cnt[4096];
// Per-group done counters for end-of-run reset: g_done[grp*32].
__device__ unsigned g_done[512];

// ============================================================================
// helpers
// ============================================================================
__device__ __forceinline__ uint32_t smem_u32(const void* p) {
    uint32_t a;
    asm("{ .reg .u64 t; cvta.to.shared.u64 t, %1; cvt.u32.u64 %0, t; }"
        : "=r"(a) : "l"(p));
    return a;
}
__device__ __forceinline__ void ldsm_x4(uint32_t& r0, uint32_t& r1,
                                        uint32_t& r2, uint32_t& r3,
                                        uint32_t addr) {
    asm volatile("ldmatrix.sync.aligned.m8n8.x4.shared.b16 {%0,%1,%2,%3}, [%4];"
                 : "=r"(r0), "=r"(r1), "=r"(r2), "=r"(r3) : "r"(addr));
}
__device__ __forceinline__ void mma16816(float* c, const uint32_t* a,
                                         uint32_t b0, uint32_t b1) {
    asm volatile(
        "mma.sync.aligned.m16n8k16.row.col.f32.f16.f16.f32 "
        "{%0,%1,%2,%3}, {%4,%5,%6,%7}, {%8,%9}, {%0,%1,%2,%3};"
        : "+f"(c[0]), "+f"(c[1]), "+f"(c[2]), "+f"(c[3])
        : "r"(a[0]), "r"(a[1]), "r"(a[2]), "r"(a[3]), "r"(b0), "r"(b1));
}
#define CP_ASYNC16(dst, src) \
    asm volatile("cp.async.cg.shared.global [%0], [%1], 16;" \
                 :: "r"(dst), "l"(src) : "memory")
#define CP_COMMIT() asm volatile("cp.async.commit_group;" ::: "memory")
#define CP_WAIT(n)  asm volatile("cp.async.wait_group %0;" :: "n"(n) : "memory")

__device__ __forceinline__ unsigned ld_acquire(const unsigned* p) {
    unsigned v;
    asm volatile("ld.acquire.gpu.global.u32 %0, [%1];"
                 : "=r"(v) : "l"(p) : "memory");
    return v;
}
__device__ __forceinline__ void st_release(unsigned* p, unsigned v) {
    asm volatile("st.release.gpu.global.u32 [%0], %1;"
                 :: "l"(p), "r"(v) : "memory");
}
__device__ __forceinline__ void red_add_release(unsigned* p, unsigned v) {
    asm volatile("red.release.gpu.global.add.u32 [%0], %1;"
                 :: "l"(p), "r"(v) : "memory");
}
__device__ __forceinline__ uint4 ldg_cg_v4(const void* p) {
    uint4 v;
    asm volatile("ld.global.cg.v4.u32 {%0,%1,%2,%3}, [%4];"
                 : "=r"(v.x), "=r"(v.y), "=r"(v.z), "=r"(v.w) : "l"(p));
    return v;
}

// Warp-autonomous wait: lanes 0..7 poll the 8 rank flags until all >= target.
__device__ __forceinline__ void warp_wait8(const unsigned* cntBase,
                                           unsigned target, int lane) {
    bool ready = true;
    if (lane < 8)
        ready = ((int)(ld_acquire(cntBase + lane * 32) - target) >= 0);
    while (!__all_sync(0xffffffffu, ready)) {
        if (lane < 8 && !ready)
            ready = ((int)(ld_acquire(cntBase + lane * 32) - target) >= 0);
    }
}

// ============================================================================
// One-time fp32 -> fp16 conversion kernels.
// ============================================================================
__global__ __launch_bounds__(256) void convert_x_h(const float* __restrict__ X) {
    size_t i = (size_t)blockIdx.x * blockDim.x + threadIdx.x;   // per float4
    float4 v = reinterpret_cast<const float4*>(X)[i];
    __half2 a = __floats2half2_rn(v.x, v.y);
    __half2 b = __floats2half2_rn(v.z, v.w);
    reinterpret_cast<uint2*>(g_Xf)[i] =
        make_uint2(*reinterpret_cast<uint32_t*>(&a),
                   *reinterpret_cast<uint32_t*>(&b));
}
__global__ __launch_bounds__(256) void convert_w_h(
    const float* __restrict__ Wf, const float* __restrict__ Wi,
    const float* __restrict__ Wo, const float* __restrict__ Wa) {
    size_t i = (size_t)blockIdx.x * blockDim.x + threadIdx.x;   // per float4
    int gate = (int)(i >> 16);
    const float* W = (gate == 0) ? Wf : (gate == 1) ? Wi : (gate == 2) ? Wo : Wa;
    float4 v = reinterpret_cast<const float4*>(W)[i & 65535];
    __half2 a = __floats2half2_rn(v.x, v.y);
    __half2 b = __floats2half2_rn(v.z, v.w);
    reinterpret_cast<uint2*>(g_Wf)[i] =
        make_uint2(*reinterpret_cast<uint32_t*>(&a),
                   *reinterpret_cast<uint32_t*>(&b));
}

// ============================================================================
// GEMM1 via fp16 mma.sync (1 term, fp32 acc), cp.async 2-stage pipeline.
// (round-8 version, verbatim)
// ============================================================================
__global__ __launch_bounds__(256, 2) void gemm_xproj_mma(
    const float* __restrict__ bf, const float* __restrict__ bi,
    const float* __restrict__ bo)
{
    extern __shared__ __align__(128) char smem[];
    const uint32_t sb = smem_u32(smem);

    const int tid  = threadIdx.x;
    const int lane = tid & 31;
    const int wid  = tid >> 5;
    const int wm   = wid >> 1;
    const int wn   = wid & 1;

    const int nTile = blockIdx.x;
    const int mBase = blockIdx.y * 128;
    const int gate  = nTile >> 2;
    const int rowG  = (nTile & 3) * 128;
    const float* bias = (gate == 0) ? bf : (gate == 1) ? bi : (gate == 2) ? bo : nullptr;

    const __half* A = g_Xf + (size_t)mBase * DIM;
    const __half* B = g_Wf + (size_t)nTile * 128 * DIM;

    float c[2][8][4];
#pragma unroll
    for (int mf = 0; mf < 2; mf++)
#pragma unroll
        for (int nf = 0; nf < 8; nf++)
#pragma unroll
            for (int q = 0; q < 4; q++) c[mf][nf][q] = 0.f;

    auto stage = [&](int chunk, int s) {
        const int kb = chunk * 64;
        const uint32_t sOff = (uint32_t)s * 32768;
#pragma unroll
        for (int it = 0; it < 4; it++) {
            int idx = tid + it * 256;
            int row = idx >> 3;
            int ch  = idx & 7;
            uint32_t off = sOff + (uint32_t)row * 128 + ((ch ^ (row & 7)) << 4);
            const size_t g = (size_t)row * DIM + kb + ch * 8;
            CP_ASYNC16(sb + off,         A + g);
            CP_ASYNC16(sb + off + 16384, B + g);
        }
        CP_COMMIT();
    };

    stage(0, 0);

    for (int chunk = 0; chunk < 8; chunk++) {
        if (chunk < 7) {
            stage(chunk + 1, (chunk + 1) & 1);
            CP_WAIT(1);
        } else {
            CP_WAIT(0);
        }
        __syncthreads();

        const uint32_t sOff = (uint32_t)(chunk & 1) * 32768;
        const uint32_t AS = sOff, BS = sOff + 16384;

#pragma unroll
        for (int ks = 0; ks < 4; ks++) {
            const int chv = ks * 2 + (lane >> 4);

            uint32_t a[2][4];
#pragma unroll
            for (int mf = 0; mf < 2; mf++) {
                const int row = wm * 32 + mf * 16 + (lane & 15);
                const uint32_t addr =
                    sb + AS + (uint32_t)row * 128 + (((chv ^ (row & 7))) << 4);
                ldsm_x4(a[mf][0], a[mf][1], a[mf][2], a[mf][3], addr);
            }
            uint32_t b[4][4];
#pragma unroll
            for (int np = 0; np < 4; np++) {
                const int row = wn * 64 + np * 16 + (lane & 15);
                const uint32_t addr =
                    sb + BS + (uint32_t)row * 128 + (((chv ^ (row & 7))) << 4);
                ldsm_x4(b[np][0], b[np][1], b[np][2], b[np][3], addr);
            }
#pragma unroll
            for (int mf = 0; mf < 2; mf++)
#pragma unroll
                for (int nf = 0; nf < 8; nf++) {
                    const int np = nf >> 1, s = nf & 1;
                    mma16816(c[mf][nf], a[mf], b[np][s], b[np][s + 2]);
                }
        }
        __syncthreads();
    }

    const int colBase = nTile * 128 + wn * 64 + (lane & 3) * 2;
    const int rBase   = mBase + wm * 32 + (lane >> 2);
#pragma unroll
    for (int nf = 0; nf < 8; nf++) {
        const int col = colBase + nf * 8;
        const int ln  = wn * 64 + nf * 8 + (lane & 3) * 2;
        float b0 = bias ? __ldg(bias + rowG + ln)     : 0.f;
        float b1 = bias ? __ldg(bias + rowG + ln + 1) : 0.f;
#pragma unroll
        for (int mf = 0; mf < 2; mf++) {
            const size_t r0 = (size_t)(rBase + mf * 16);
            float2 o0 = make_float2(c[mf][nf][0] + b0, c[mf][nf][1] + b1);
            float2 o1 = make_float2(c[mf][nf][2] + b0, c[mf][nf][3] + b1);
            *reinterpret_cast<float2*>(g_Y + r0 * N4 + col)       = o0;
            *reinterpret_cast<float2*>(g_Y + (r0 + 8) * N4 + col) = o1;
        }
    }
}

// ============================================================================
// Persistent tensor-core recurrence: fragment exchange + per-rank flags.
// 128 CTAs = 16 groups (mTile, 16 rows) x 8 ranks (nTile, 64 cols), 256 thr.
// W fragments in registers. h(t) posted to g_hfrag in mma A-fragment layout.
// Sync: per-rank single-writer release flags; each warp waits autonomously
// (lanes 0..7 poll + ballot). One __syncthreads per step (pre-post ordering).
// Flags reset at kernel end via per-group done-join (replay-safe).
// ============================================================================
__device__ __forceinline__ float sigf(float x) {
    return 1.f / (1.f + __expf(-x));
}
__device__ __forceinline__ float tanh_fast(float x) {
    return 2.f / (1.f + __expf(-2.f * x)) - 1.f;
}

__global__ __launch_bounds__(256, 1) void lstm_persistent_tc(
    const float* __restrict__ Waa,
    const float* __restrict__ ba,
    float*       __restrict__ out,
    float*       __restrict__ hn)
{
    extern __shared__ __align__(128) char sm[];
    const uint32_t sb = smem_u32(sm);

    const int tid  = threadIdx.x;
    const int lane = tid & 31;
    const int wid  = tid >> 5;                 // 0..7: n-subtile
    const int grp  = blockIdx.x >> 3;          // mTile group 0..15
    const int rank = blockIdx.x & 7;           // nTile rank
    const int m0   = grp * 16;
    const int n0   = rank * 64;

    // --- one-time: Waa[n0+n][k] -> smem fp16 (swizzled) for B preload ---
#pragma unroll
    for (int i = 0; i < 16; i++) {
        int idx = tid + i * 256;          // n(0..63) x chunk(0..63)
        int n = idx >> 6;
        int c = idx & 63;
        const float* src = Waa + (size_t)(n0 + n) * HID + c * 8;
        float4 v0 = *reinterpret_cast<const float4*>(src);
        float4 v1 = *reinterpret_cast<const float4*>(src + 4);
        __half2 hh[4];
        hh[0] = __floats2half2_rn(v0.x, v0.y);
        hh[1] = __floats2half2_rn(v0.z, v0.w);
        hh[2] = __floats2half2_rn(v1.x, v1.y);
        hh[3] = __floats2half2_rn(v1.z, v1.w);
        uint32_t off = (uint32_t)n * 1024 + ((c ^ (n & 7)) << 4);
        *reinterpret_cast<uint4*>(sm + off) = *reinterpret_cast<uint4*>(hh);
    }
    __syncthreads();

    // --- preload all B (W_aa) fragments to registers: 32 k16-steps ---
    uint32_t bLo[32], bHi[32];
    {
        const int rB = wid * 8 + (lane & 7);
        const uint32_t bRow = sb + (uint32_t)rB * 1024;
        const int swB = rB & 7;
#pragma unroll
        for (int j = 0; j < 16; j++) {            // k32 steps
            const int chB = j * 4 + (lane >> 3);
            uint32_t b[4];
            ldsm_x4(b[0], b[1], b[2], b[3], bRow + ((chB ^ swB) << 4));
            bLo[2 * j]     = b[0]; bHi[2 * j]     = b[1];
            bLo[2 * j + 1] = b[2]; bHi[2 * j + 1] = b[3];
        }
    }

    // Per-thread coordinates (mma c-frag layout).
    const int nn   = n0 + wid * 8 + (lane & 3) * 2;   // global col (even)
    const int row0 = lane >> 2;
    const int mr0  = m0 + row0;
    const int mr1  = mr0 + 8;
    const float bav0 = ba[nn];
    const float bav1 = ba[nn + 1];

    // Producer fragment address (constant): words (row0,nn) + (row0+8,nn).
    const uint32_t sP = (uint32_t)(nn >> 4);
    const uint32_t lP = (uint32_t)row0 * 4 + (uint32_t)((nn >> 1) & 3);
    const uint32_t wP = (uint32_t)((nn >> 3) & 1) * 2;
    const uint32_t prodOff = sP * 512 + lP * 16 + wP * 4;

    unsigned char* fragBase = g_hfrag + (size_t)grp * 32768;
    unsigned* cntBase = &g_cnt[grp * 8 * 32];
    unsigned* myCnt   = cntBase + rank * 32;

    float cc[4];
#pragma unroll
    for (int j = 0; j < 4; j++) cc[j] = 0.f;

    // Y prefetch for t=0.
    float2 pf[2][4];
    {
        const float* yb = g_Y;
#pragma unroll
        for (int g = 0; g < 4; g++) {
            pf[0][g] = *reinterpret_cast<const float2*>(
                yb + (size_t)mr0 * N4 + g * HID + nn);
            pf[1][g] = *reinterpret_cast<const float2*>(
                yb + (size_t)mr1 * N4 + g * HID + nn);
        }
    }

    for (int t = 0; t < T_LEN; t++) {
        float c0[4] = {0.f, 0.f, 0.f, 0.f};
        float c1[4] = {0.f, 0.f, 0.f, 0.f};
        float c2[4] = {0.f, 0.f, 0.f, 0.f};
        float c3[4] = {0.f, 0.f, 0.f, 0.f};

        if (t > 0) {
            // Warp-autonomous wait: all 8 ranks posted h(t-1) (flag >= t).
            warp_wait8(cntBase, (unsigned)t, lane);

            const unsigned char* fb =
                fragBase + (size_t)((t - 1) & 1) * 16384 + (uint32_t)lane * 16;
#pragma unroll
            for (int s = 0; s < 32; s++) {
                uint4 av = ldg_cg_v4(fb + (uint32_t)s * 512);
                uint32_t a[4] = {av.x, av.y, av.z, av.w};
                const int q = s & 3;
                if (q == 0)      mma16816(c0, a, bLo[s], bHi[s]);
                else if (q == 1) mma16816(c1, a, bLo[s], bHi[s]);
                else if (q == 2) mma16816(c2, a, bLo[s], bHi[s]);
                else             mma16816(c3, a, bLo[s], bHi[s]);
            }
        }

        // Gates + state update (c in regs).
        float acc[4];
#pragma unroll
        for (int j = 0; j < 4; j++)
            acc[j] = (c0[j] + c1[j]) + (c2[j] + c3[j]);

        float hv[4];
#pragma unroll
        for (int r = 0; r < 2; r++) {
            float a0 = acc[r * 2 + 0] + bav0;
            float a1 = acc[r * 2 + 1] + bav1;
            float f0 = sigf(pf[r][0].x + a0), f1 = sigf(pf[r][0].y + a1);
            float i0 = sigf(pf[r][1].x + a0), i1 = sigf(pf[r][1].y + a1);
            float o0 = sigf(pf[r][2].x + a0), o1 = sigf(pf[r][2].y + a1);
            float g0 = tanh_fast(pf[r][3].x + a0);
            float g1 = tanh_fast(pf[r][3].y + a1);
            cc[r * 2 + 0] = f0 * cc[r * 2 + 0] + i0 * g0;
            cc[r * 2 + 1] = f1 * cc[r * 2 + 1] + i1 * g1;
            hv[r * 2 + 0] = o0 * tanh_fast(cc[r * 2 + 0]);
            hv[r * 2 + 1] = o1 * tanh_fast(cc[r * 2 + 1]);
        }

        if (t < T_LEN - 1) {
            // Post h(t) fragment words.
            __half2 h2a = __floats2half2_rn(hv[0], hv[1]);   // (row0, nn)
            __half2 h2b = __floats2half2_rn(hv[2], hv[3]);   // (row0+8, nn)
            uint2 v = make_uint2(*reinterpret_cast<uint32_t*>(&h2a),
                                 *reinterpret_cast<uint32_t*>(&h2b));
            *reinterpret_cast<uint2*>(
                fragBase + (size_t)(t & 1) * 16384 + prodOff) = v;
        }

        // fp32 h to out (off the group's critical path).
        {
            float* ob = out + ((size_t)t * BSZ) * HID;
            *reinterpret_cast<float2*>(ob + (size_t)mr0 * HID + nn) =
                make_float2(hv[0], hv[1]);
            *reinterpret_cast<float2*>(ob + (size_t)mr1 * HID + nn) =
                make_float2(hv[2], hv[3]);
            if (hn && t == T_LEN - 1) {
                *reinterpret_cast<float2*>(hn + (size_t)mr0 * HID + nn) =
                    make_float2(hv[0], hv[1]);
                *reinterpret_cast<float2*>(hn + (size_t)mr1 * HID + nn) =
                    make_float2(hv[2], hv[3]);
            }
        }

        if (t < T_LEN - 1) {
            // Prefetch Y for t+1 (in flight during next wait).
            const float* yb = g_Y + (size_t)(t + 1) * BSZ * N4;
#pragma unroll
            for (int g = 0; g < 4; g++) {
                pf[0][g] = *reinterpret_cast<const float2*>(
                    yb + (size_t)mr0 * N4 + g * HID + nn);
                pf[1][g] = *reinterpret_cast<const float2*>(
                    yb + (size_t)mr1 * N4 + g * HID + nn);
            }

            // Order all 256 threads' frag stores, then single-writer release.
            __syncthreads();
            if (tid == 0) st_release(myCnt, (unsigned)(t + 1));
        }
    }

    // End-of-run: per-group join, rank 0 resets flags (replay-safe zeros).
    __syncthreads();
    unsigned* donep = &g_done[grp * 32];
    if (tid == 0) red_add_release(donep, 1u);
    if (rank == 0 && tid == 0) {
        while ((int)(ld_acquire(donep) - 8u) < 0) { }
#pragma unroll
        for (int r = 0; r < 8; r++) cntBase[r * 32] = 0u;
        __threadfence();
        *donep = 0u;
    }
}

// ---------------------------------------------------------------------------
extern "C" void kernel_launch(void* const* d_in, const int* in_sizes, int n_in,
                              void* d_out, int out_size)
{
    (void)in_sizes; (void)n_in;
    const float* X   = (const float*)d_in[0];
    const float* Wf  = (const float*)d_in[1];
    const float* Wi  = (const float*)d_in[2];
    const float* Wo  = (const float*)d_in[3];
    const float* Wa  = (const float*)d_in[4];
    const float* Waa = (const float*)d_in[5];
    const float* bf  = (const float*)d_in[6];
    const float* bi  = (const float*)d_in[7];
    const float* bo  = (const float*)d_in[8];
    const float* ba  = (const float*)d_in[9];
    float* out = (float*)d_out;

    const int gemm_smem = 65536;    // 64 KB
    const int rec_smem  = 65536;    // W staging during init only
    static bool attr_set = false;
    if (!attr_set) {
        cudaFuncSetAttribute(gemm_xproj_mma,
                             cudaFuncAttributeMaxDynamicSharedMemorySize,
                             gemm_smem);
        cudaFuncSetAttribute(lstm_persistent_tc,
                             cudaFuncAttributeMaxDynamicSharedMemorySize,
                             rec_smem);
        attr_set = true;
    }

    convert_x_h<<<65536, 256>>>(X);
    convert_w_h<<<1024, 256>>>(Wf, Wi, Wo, Wa);

    dim3 g1(16, 1024);
    gemm_xproj_mma<<<g1, 256, gemm_smem>>>(bf, bi, bo);

    const size_t step_elems = (size_t)BSZ * HID;
    const size_t outs_elems = (size_t)T_LEN * step_elems;
    float* hn_ptr = ((size_t)out_size >= outs_elems + step_elems)
                        ? out + outs_elems : nullptr;

    lstm_persistent_tc<<<128, 256, rec_smem>>>(Waa, ba, out, hn_ptr);
}